// round 13
// baseline (speedup 1.0000x reference)
#include <cuda_runtime.h>
#include <cuda_fp16.h>
#include <cstdint>
#include <math.h>

// ---------------------------------------------------------------------------
// Problem: B=64, N=236, C=768, H=8, D=96.  M = B*N = 15104 = 118*128.
// Scratch (static device globals -- no runtime allocation allowed)
// ---------------------------------------------------------------------------
__device__ __half g_qkvh[(size_t)15104 * 2304];  // [B*N, 3C] fp16
__device__ float  g_S[(size_t)512 * 236 * 236];  // [B*H, 236, 236] fp32 logits
__device__ __half g_P[(size_t)512 * 236 * 240];  // probs fp16, K-padded to 240
__device__ __half g_vth[(size_t)512 * 96 * 240]; // V^T fp16, padded to 240
__device__ __half g_atth[(size_t)15104 * 768];   // attention out fp16
__device__ __half g_xh[(size_t)15104 * 768];     // x fp16
__device__ __half g_wh[(size_t)2304 * 768];      // qkv_w fp16
__device__ __half g_pwh[(size_t)768 * 768];      // proj_w fp16

// ---------------------------------------------------------------------------
__device__ __forceinline__ uint32_t smem_u32(const void* p) {
    uint32_t a;
    asm("{ .reg .u64 t; cvta.to.shared.u64 t, %1; cvt.u32.u64 %0, t; }" : "=r"(a) : "l"(p));
    return a;
}
__device__ __forceinline__ void mma_f16(float* c, const uint32_t* a, const uint32_t* b) {
    asm volatile(
        "mma.sync.aligned.m16n8k16.row.col.f32.f16.f16.f32 "
        "{%0,%1,%2,%3}, {%4,%5,%6,%7}, {%8,%9}, {%0,%1,%2,%3};"
        : "+f"(c[0]), "+f"(c[1]), "+f"(c[2]), "+f"(c[3])
        : "r"(a[0]), "r"(a[1]), "r"(a[2]), "r"(a[3]), "r"(b[0]), "r"(b[1]));
}
#define LDMX4(r, addr) \
    asm volatile("ldmatrix.sync.aligned.m8n8.x4.shared.b16 {%0,%1,%2,%3}, [%4];" \
                 : "=r"((r)[0]), "=r"((r)[1]), "=r"((r)[2]), "=r"((r)[3]) : "r"(addr))
// cp.async 16B; when !pred copies 0 source bytes -> dst 16B zero-filled
__device__ __forceinline__ void cpa16(uint32_t dst, const void* src, bool pred) {
    int sz = pred ? 16 : 0;
    asm volatile("cp.async.cg.shared.global [%0], [%1], 16, %2;"
                 :: "r"(dst), "l"(src), "r"(sz) : "memory");
}

// ---------------------------------------------------------------------------
// fp16 tensor-core batched NT GEMM: C[m,n] = alpha*sum_k A[m,k]*B[n,k] (+bias[n])
// CTA tile 128x256x32, 256 threads (8 warps, 2x4), warp tile 64x64,
// occupancy 1 (255-reg budget: acc=128 floats/thread + live fragments).
// 4-stage cp.async pipeline, one __syncthreads per k-tile, ldmatrix loads.
// smem per stage: A 128x40h (10240 B) + B 256x40h (20480 B) = 30720 B.
// 4 stages = 122880 B.
// ---------------------------------------------------------------------------
template<bool OUT_HALF, bool ADD_BIAS>
__global__ void __launch_bounds__(256, 1)
hgemm(const __half* __restrict__ Ag, const __half* __restrict__ Bg,
      const float* __restrict__ bias, void* __restrict__ Cv,
      int M, int N, int K, int lda, int ldb, int ldc,
      int HB, long sAb, long sAh, long sBb, long sBh, long sCb, long sCh,
      float alpha)
{
    extern __shared__ __half smem[];

    const int z  = blockIdx.z;
    const int hb = z % HB, bb = z / HB;
    const __half* A = Ag + (size_t)bb * sAb + (size_t)hb * sAh;
    const __half* B = Bg + (size_t)bb * sBb + (size_t)hb * sBh;

    const int bm = blockIdx.x * 128, bn = blockIdx.y * 256;
    const int tid = threadIdx.x, lane = tid & 31, wid = tid >> 5;
    const int wm = wid & 1, wn = wid >> 1;     // warp m (x64), warp n (x64)
    const int q = lane >> 2, r = lane & 3;
    const uint32_t sbase = smem_u32(smem);

    // ldmatrix lane address components
    const int lt = lane >> 3, li = lane & 7;
    const int aRow = wm * 64 + (lt & 1) * 8 + li;    // + mt*16
    const int aCol = (lt >> 1) * 16;                  // bytes; + ks*2
    const int bRow = wn * 64 + (lt >> 1) * 8 + li;    // + jp*16
    const int bCol = (lt & 1) * 16;                   // bytes; + ks*2

    float acc[4][8][4];
#pragma unroll
    for (int mt = 0; mt < 4; mt++)
#pragma unroll
        for (int j = 0; j < 8; j++)
#pragma unroll
            for (int u = 0; u < 4; u++) acc[mt][j][u] = 0.0f;

    // per tile: A 128x4 chunks = 512, B 256x4 = 1024 chunks (16B each)
    auto issue = [&](int stage, int t) {
        const int k0 = t * 32;
#pragma unroll
        for (int i = 0; i < 2; i++) {   // A
            int cid = tid + i * 256;
            int m = cid >> 2, c8 = cid & 3;
            int gc = k0 + c8 * 8;
            int gr = bm + m;
            bool p = (gr < M) && (gc + 8 <= K);
            const __half* src = p ? (A + (size_t)gr * lda + gc) : A;
            cpa16(sbase + (uint32_t)(stage * 30720 + m * 80 + c8 * 16), src, p);
        }
#pragma unroll
        for (int i = 0; i < 4; i++) {   // B
            int cid = tid + i * 256;
            int m = cid >> 2, c8 = cid & 3;
            int gc = k0 + c8 * 8;
            int gr = bn + m;
            bool p = (gr < N) && (gc + 8 <= K);
            const __half* src = p ? (B + (size_t)gr * ldb + gc) : B;
            cpa16(sbase + (uint32_t)(stage * 30720 + 10240 + m * 80 + c8 * 16), src, p);
        }
    };

    auto compute = [&](int stage) {
        const uint32_t baseA = sbase + stage * 30720;
        const uint32_t baseB = baseA + 10240;
#pragma unroll
        for (int ks = 0; ks < 32; ks += 16) {
            uint32_t a[4][4], b[4][4];
#pragma unroll
            for (int mt = 0; mt < 4; mt++)
                LDMX4(a[mt], baseA + (uint32_t)((aRow + mt * 16) * 80 + aCol + ks * 2));
#pragma unroll
            for (int jp = 0; jp < 4; jp++)
                LDMX4(b[jp], baseB + (uint32_t)((bRow + jp * 16) * 80 + bCol + ks * 2));
#pragma unroll
            for (int mt = 0; mt < 4; mt++)
#pragma unroll
                for (int j = 0; j < 8; j++) {
                    uint32_t bb2[2] = { b[j >> 1][(j & 1) * 2], b[j >> 1][(j & 1) * 2 + 1] };
                    mma_f16(acc[mt][j], a[mt], bb2);
                }
        }
    };

    const int ntiles = (K + 31) / 32;

    // prologue: fill 3 of 4 stages
#pragma unroll
    for (int p = 0; p < 3; p++) {
        if (p < ntiles) issue(p, p);
        asm volatile("cp.async.commit_group;" ::: "memory");
    }

    for (int t = 0; t < ntiles; t++) {
        asm volatile("cp.async.wait_group 2;" ::: "memory");   // tile t ready
        __syncthreads();
        if (t + 3 < ntiles) issue((t + 3) & 3, t + 3);
        asm volatile("cp.async.commit_group;" ::: "memory");
        compute(t & 3);
    }

    // epilogue
#pragma unroll
    for (int mt = 0; mt < 4; mt++) {
#pragma unroll
        for (int j = 0; j < 8; j++) {
            int col = bn + wn * 64 + j * 8 + r * 2;
            if (col >= N) continue;
            int row0 = bm + wm * 64 + mt * 16 + q;
            float bx = 0.f, by = 0.f;
            if (ADD_BIAS) { bx = bias[col]; by = bias[col + 1]; }
#pragma unroll
            for (int h = 0; h < 2; h++) {
                int row = row0 + h * 8;
                if (row >= M) continue;
                float vx = acc[mt][j][h * 2 + 0] * alpha + bx;
                float vy = acc[mt][j][h * 2 + 1] * alpha + by;
                if (OUT_HALF) {
                    __half2* dst = reinterpret_cast<__half2*>(
                        (__half*)Cv + (size_t)bb * sCb + (size_t)hb * sCh + (size_t)row * ldc + col);
                    *dst = __floats2half2_rn(vx, vy);
                } else {
                    float2* dst = reinterpret_cast<float2*>(
                        (float*)Cv + (size_t)bb * sCb + (size_t)hb * sCh + (size_t)row * ldc + col);
                    *dst = make_float2(vx, vy);
                }
            }
        }
    }
}

// ---------------------------------------------------------------------------
// fp32 -> fp16 conversion (4 floats / thread)
// ---------------------------------------------------------------------------
__global__ void cvt_h(const float* __restrict__ in, __half* __restrict__ out, int n4)
{
    int i = blockIdx.x * blockDim.x + threadIdx.x;
    if (i < n4) {
        float4 v = reinterpret_cast<const float4*>(in)[i];
        uint2 u;
        __half2 h0 = __floats2half2_rn(v.x, v.y);
        __half2 h1 = __floats2half2_rn(v.z, v.w);
        u.x = *reinterpret_cast<uint32_t*>(&h0);
        u.y = *reinterpret_cast<uint32_t*>(&h1);
        reinterpret_cast<uint2*>(out)[i] = u;
    }
}

// ---------------------------------------------------------------------------
// V transpose fp16: vth[bh][d][tok] = qkvh[(b*236+tok)*2304 + 1536 + h*96 + d]
// Output pitch 240 (tok 236..239 zero-filled).
// ---------------------------------------------------------------------------
__global__ void vtrans_kernel(const __half* __restrict__ qkvh, __half* __restrict__ vt)
{
    __shared__ float t[32][33];
    const int bh = blockIdx.z;
    const int b = bh >> 3, h = bh & 7;
    const int t0 = blockIdx.x * 32;
    const int d0 = blockIdx.y * 32;
    const int tx = threadIdx.x, ty = threadIdx.y;

#pragma unroll
    for (int r = ty; r < 32; r += 8) {
        int tok = t0 + r;
        int d = d0 + tx;
        float v = 0.f;
        if (tok < 236)
            v = __half2float(qkvh[(size_t)(b * 236 + tok) * 2304 + 1536 + h * 96 + d]);
        t[r][tx] = v;
    }
    __syncthreads();
#pragma unroll
    for (int r = ty; r < 32; r += 8) {
        int d = d0 + r;
        int tok = t0 + tx;
        if (tok < 240)
            vt[((size_t)bh * 96 + d) * 240 + tok] =
                (tok < 236) ? __float2half_rn(t[tx][r]) : __float2half_rn(0.f);
    }
}

// ---------------------------------------------------------------------------
// Block edits + softmax. Reads fp32 logits S[bh][236][236], writes fp16
// probabilities P[bh][236][240] (cols 236..239 zeroed).
// ---------------------------------------------------------------------------
__global__ void softmax_edit_kernel(const float* __restrict__ S, __half* __restrict__ P)
{
    const int r  = blockIdx.x;   // 0..235
    const int bh = blockIdx.y;   // 0..511
    const float* srow = S + ((size_t)bh * 236 + r) * 236;
    __half* prow = P + ((size_t)bh * 236 + r) * 240;
    const int c = threadIdx.x;

    float v = -1e30f;
    if (c < 236) {
        float s;
        if (r < 196) {
            if (c >= 216)      s = srow[c - 20];      // copy uses PRE-bias values
            else if (c >= 196) s = srow[c] - 100.0f;
            else               s = srow[c];
        } else if (r < 216) {
            s = srow[c] - ((c >= 216) ? 100.0f : 0.0f);
        } else {
            s = srow[c] - ((c >= 196 && c < 216) ? 100.0f : 0.0f);
        }
        v = s;
    }

    __shared__ float red[8];
    float m = v;
#pragma unroll
    for (int o = 16; o > 0; o >>= 1) m = fmaxf(m, __shfl_xor_sync(0xffffffffu, m, o));
    if ((c & 31) == 0) red[c >> 5] = m;
    __syncthreads();
    float mx = fmaxf(fmaxf(fmaxf(red[0], red[1]), fmaxf(red[2], red[3])),
                     fmaxf(fmaxf(red[4], red[5]), fmaxf(red[6], red[7])));

    float e = (c < 236) ? expf(v - mx) : 0.0f;
    float ssum = e;
#pragma unroll
    for (int o = 16; o > 0; o >>= 1) ssum += __shfl_xor_sync(0xffffffffu, ssum, o);
    __syncthreads();
    if ((c & 31) == 0) red[c >> 5] = ssum;
    __syncthreads();
    float tot = red[0] + red[1] + red[2] + red[3] + red[4] + red[5] + red[6] + red[7];

    if (c < 240) prow[c] = (c < 236) ? __float2half_rn(e / tot) : __float2half_rn(0.f);
}

// ---------------------------------------------------------------------------
extern "C" void kernel_launch(void* const* d_in, const int* in_sizes, int n_in,
                              void* d_out, int out_size)
{
    const float* x      = (const float*)d_in[0];   // [64,236,768]
    const float* qkv_w  = (const float*)d_in[1];   // [2304,768]
    const float* proj_w = (const float*)d_in[2];   // [768,768]
    const float* proj_b = (const float*)d_in[3];   // [768]
    float* out = (float*)d_out;                    // [64,236,768]

    __half *qkvh, *P, *vth, *atth, *xh, *wh, *pwh;
    float *S;
    cudaGetSymbolAddress((void**)&qkvh, g_qkvh);
    cudaGetSymbolAddress((void**)&S,    g_S);
    cudaGetSymbolAddress((void**)&P,    g_P);
    cudaGetSymbolAddress((void**)&vth,  g_vth);
    cudaGetSymbolAddress((void**)&atth, g_atth);
    cudaGetSymbolAddress((void**)&xh,   g_xh);
    cudaGetSymbolAddress((void**)&wh,   g_wh);
    cudaGetSymbolAddress((void**)&pwh,  g_pwh);

    const int SMEM = 122880;   // 4 stages x 30720 B
    cudaFuncSetAttribute(hgemm<true,  false>, cudaFuncAttributeMaxDynamicSharedMemorySize, SMEM);
    cudaFuncSetAttribute(hgemm<false, false>, cudaFuncAttributeMaxDynamicSharedMemorySize, SMEM);
    cudaFuncSetAttribute(hgemm<false, true>,  cudaFuncAttributeMaxDynamicSharedMemorySize, SMEM);

    const float scale = 0.10206207261596575f;      // 1/sqrt(96)

    // 0) convert inputs to fp16
    cvt_h<<<(15104 * 768 / 4 + 255) / 256, 256>>>(x, xh, 15104 * 768 / 4);
    cvt_h<<<(2304 * 768 / 4 + 255) / 256, 256>>>(qkv_w, wh, 2304 * 768 / 4);
    cvt_h<<<(768 * 768 / 4 + 255) / 256, 256>>>(proj_w, pwh, 768 * 768 / 4);

    // 1) qkvh = x @ qkv_w^T            [15104 x 2304], K=768, fp16 out
    hgemm<true, false><<<dim3(118, 9, 1), 256, SMEM>>>(
        xh, wh, nullptr, qkvh,
        15104, 2304, 768, 768, 768, 2304,
        1, 0, 0, 0, 0, 0, 0, 1.0f);

    // 2) S[bh] = (Q @ K^T) * scale     512 batches, 236x236, K=96, fp32 out
    hgemm<false, false><<<dim3(2, 1, 512), 256, SMEM>>>(
        qkvh, qkvh + 768, nullptr, S,
        236, 236, 96, 2304, 2304, 236,
        8, (long)236 * 2304, 96, (long)236 * 2304, 96,
        (long)8 * 236 * 236, (long)236 * 236,
        scale);

    // 3) block edits + softmax: S fp32 -> P fp16 (padded to 240)
    softmax_edit_kernel<<<dim3(236, 512), 256>>>(S, P);

    // 3b) V transpose -> vth fp16 (padded to 240)
    vtrans_kernel<<<dim3(8, 3, 512), dim3(32, 8)>>>(qkvh, vth);

    // 4) atth[bh] = P @ vth^T          512 batches, 236x96, K=240(padded), fp16 out
    hgemm<true, false><<<dim3(2, 1, 512), 256, SMEM>>>(
        P, vth, nullptr, atth,
        236, 96, 240, 240, 240, 768,
        8, (long)8 * 236 * 240, (long)236 * 240,
        (long)8 * 96 * 240, (long)96 * 240,
        (long)236 * 768, 96,
        1.0f);

    // 5) out = atth @ proj_w^T + proj_b  [15104 x 768], K=768, fp32 out + bias
    hgemm<false, true><<<dim3(118, 3, 1), 256, SMEM>>>(
        atth, pwh, proj_b, out,
        15104, 768, 768, 768, 768, 768,
        1, 0, 0, 0, 0, 0, 0, 1.0f);
}

// round 14
// speedup vs baseline: 1.2789x; 1.2789x over previous
#include <cuda_runtime.h>
#include <cuda_fp16.h>
#include <cstdint>
#include <math.h>

// ---------------------------------------------------------------------------
// Problem: B=64, N=236, C=768, H=8, D=96.  M = B*N = 15104 = 118*128.
// Scratch (static device globals -- no runtime allocation allowed)
// ---------------------------------------------------------------------------
__device__ __half g_qkvh[(size_t)15104 * 2304];  // [B*N, 3C] fp16
__device__ __half g_P[(size_t)512 * 236 * 240];  // probs fp16, K-padded to 240
__device__ __half g_vth[(size_t)512 * 96 * 240]; // V^T fp16, padded to 240
__device__ __half g_atth[(size_t)15104 * 768];   // attention out fp16
__device__ __half g_xh[(size_t)15104 * 768];     // x fp16
__device__ __half g_wh[(size_t)2304 * 768];      // qkv_w fp16
__device__ __half g_pwh[(size_t)768 * 768];      // proj_w fp16

// ---------------------------------------------------------------------------
__device__ __forceinline__ uint32_t smem_u32(const void* p) {
    uint32_t a;
    asm("{ .reg .u64 t; cvta.to.shared.u64 t, %1; cvt.u32.u64 %0, t; }" : "=r"(a) : "l"(p));
    return a;
}
__device__ __forceinline__ void mma_f16(float* c, const uint32_t* a, const uint32_t* b) {
    asm volatile(
        "mma.sync.aligned.m16n8k16.row.col.f32.f16.f16.f32 "
        "{%0,%1,%2,%3}, {%4,%5,%6,%7}, {%8,%9}, {%0,%1,%2,%3};"
        : "+f"(c[0]), "+f"(c[1]), "+f"(c[2]), "+f"(c[3])
        : "r"(a[0]), "r"(a[1]), "r"(a[2]), "r"(a[3]), "r"(b[0]), "r"(b[1]));
}
#define LDMX4(r, addr) \
    asm volatile("ldmatrix.sync.aligned.m8n8.x4.shared.b16 {%0,%1,%2,%3}, [%4];" \
                 : "=r"((r)[0]), "=r"((r)[1]), "=r"((r)[2]), "=r"((r)[3]) : "r"(addr))
// cp.async 16B; when !pred copies 0 source bytes -> dst 16B zero-filled
__device__ __forceinline__ void cpa16(uint32_t dst, const void* src, bool pred) {
    int sz = pred ? 16 : 0;
    asm volatile("cp.async.cg.shared.global [%0], [%1], 16, %2;"
                 :: "r"(dst), "l"(src), "r"(sz) : "memory");
}

// ---------------------------------------------------------------------------
// fp16 tensor-core batched NT GEMM (R12 engine -- best measured config):
// C[m,n] = alpha*sum_k A[m,k]*B[n,k] (+bias[n]); fp32 accum; C fp32/fp16.
// 128x128x32 tile, 256 threads, 8 warps (4x2), warp tile 32x64,
// 4-stage cp.async pipeline, one __syncthreads per k-tile, ldmatrix loads.
// smem per stage: A 128x40h + B 128x40h = 20480 B; 4 stages = 81920 B.
// ---------------------------------------------------------------------------
template<bool OUT_HALF, bool ADD_BIAS>
__global__ void __launch_bounds__(256, 2)
hgemm(const __half* __restrict__ Ag, const __half* __restrict__ Bg,
      const float* __restrict__ bias, void* __restrict__ Cv,
      int M, int N, int K, int lda, int ldb, int ldc,
      int HB, long sAb, long sAh, long sBb, long sBh, long sCb, long sCh,
      float alpha)
{
    extern __shared__ __half smem[];

    const int z  = blockIdx.z;
    const int hb = z % HB, bb = z / HB;
    const __half* A = Ag + (size_t)bb * sAb + (size_t)hb * sAh;
    const __half* B = Bg + (size_t)bb * sBb + (size_t)hb * sBh;

    const int bm = blockIdx.x * 128, bn = blockIdx.y * 128;
    const int tid = threadIdx.x, lane = tid & 31, wid = tid >> 5;
    const int wr = wid & 3, wc = wid >> 2;
    const int q = lane >> 2, r = lane & 3;
    const uint32_t sbase = smem_u32(smem);

    const int lt = lane >> 3, li = lane & 7;
    const int aRow = wr * 32 + (lt & 1) * 8 + li;
    const int aCol = (lt >> 1) * 16;
    const int bRow = wc * 64 + (lt >> 1) * 8 + li;
    const int bCol = (lt & 1) * 16;

    float acc[2][8][4];
#pragma unroll
    for (int t2 = 0; t2 < 2; t2++)
#pragma unroll
        for (int j = 0; j < 8; j++)
#pragma unroll
            for (int u = 0; u < 4; u++) acc[t2][j][u] = 0.0f;

    auto issue = [&](int stage, int t) {
        const int k0 = t * 32;
#pragma unroll
        for (int i = 0; i < 2; i++) {   // A
            int cid = tid + i * 256;
            int m = cid >> 2, c8 = cid & 3;
            int gc = k0 + c8 * 8;
            int gr = bm + m;
            bool p = (gr < M) && (gc + 8 <= K);
            const __half* src = p ? (A + (size_t)gr * lda + gc) : A;
            cpa16(sbase + (uint32_t)(stage * 20480 + m * 80 + c8 * 16), src, p);
        }
#pragma unroll
        for (int i = 0; i < 2; i++) {   // B
            int cid = tid + i * 256;
            int m = cid >> 2, c8 = cid & 3;
            int gc = k0 + c8 * 8;
            int gr = bn + m;
            bool p = (gr < N) && (gc + 8 <= K);
            const __half* src = p ? (B + (size_t)gr * ldb + gc) : B;
            cpa16(sbase + (uint32_t)(stage * 20480 + 10240 + m * 80 + c8 * 16), src, p);
        }
    };

    auto compute = [&](int stage) {
        const uint32_t baseA = sbase + stage * 20480;
        const uint32_t baseB = baseA + 10240;
#pragma unroll
        for (int ks = 0; ks < 32; ks += 16) {
            uint32_t a[2][4], b[4][4];
#pragma unroll
            for (int t2 = 0; t2 < 2; t2++)
                LDMX4(a[t2], baseA + (uint32_t)((aRow + t2 * 16) * 80 + aCol + ks * 2));
#pragma unroll
            for (int jp = 0; jp < 4; jp++)
                LDMX4(b[jp], baseB + (uint32_t)((bRow + jp * 16) * 80 + bCol + ks * 2));
#pragma unroll
            for (int t2 = 0; t2 < 2; t2++)
#pragma unroll
                for (int j = 0; j < 8; j++) {
                    uint32_t bb2[2] = { b[j >> 1][(j & 1) * 2], b[j >> 1][(j & 1) * 2 + 1] };
                    mma_f16(acc[t2][j], a[t2], bb2);
                }
        }
    };

    const int ntiles = (K + 31) / 32;

#pragma unroll
    for (int p = 0; p < 3; p++) {
        if (p < ntiles) issue(p, p);
        asm volatile("cp.async.commit_group;" ::: "memory");
    }

    for (int t = 0; t < ntiles; t++) {
        asm volatile("cp.async.wait_group 2;" ::: "memory");
        __syncthreads();
        if (t + 3 < ntiles) issue((t + 3) & 3, t + 3);
        asm volatile("cp.async.commit_group;" ::: "memory");
        compute(t & 3);
    }

#pragma unroll
    for (int t2 = 0; t2 < 2; t2++) {
#pragma unroll
        for (int j = 0; j < 8; j++) {
            int col = bn + wc * 64 + j * 8 + r * 2;
            if (col >= N) continue;
            int row0 = bm + wr * 32 + t2 * 16 + q;
            float bx = 0.f, by = 0.f;
            if (ADD_BIAS) { bx = bias[col]; by = bias[col + 1]; }
#pragma unroll
            for (int h = 0; h < 2; h++) {
                int row = row0 + h * 8;
                if (row >= M) continue;
                float vx = acc[t2][j][h * 2 + 0] * alpha + bx;
                float vy = acc[t2][j][h * 2 + 1] * alpha + by;
                if (OUT_HALF) {
                    __half2* dst = reinterpret_cast<__half2*>(
                        (__half*)Cv + (size_t)bb * sCb + (size_t)hb * sCh + (size_t)row * ldc + col);
                    *dst = __floats2half2_rn(vx, vy);
                } else {
                    float2* dst = reinterpret_cast<float2*>(
                        (float*)Cv + (size_t)bb * sCb + (size_t)hb * sCh + (size_t)row * ldc + col);
                    *dst = make_float2(vx, vy);
                }
            }
        }
    }
}

// ---------------------------------------------------------------------------
// Fused QK^T * scale + block edits + softmax -> P fp16.
// One CTA = 128 query rows x ALL 236 key cols of one (b,h) batch.
// CTA tile 128x256x32 (cols 236..255 zero via predication, masked in softmax).
// 8 warps (2m x 4n), warp tile 64x64, occ 1. After mainloop, logits staged in
// smem (pitch 257 floats), edits + row softmax + fp16 P write (pitch 240).
// smem: max(4 stages x 30720 = 122880, 128*257*4 = 131584) = 131584 B.
// ---------------------------------------------------------------------------
__global__ void __launch_bounds__(256, 1)
qk_softmax(const __half* __restrict__ qkvh, __half* __restrict__ P, float scale)
{
    extern __shared__ __half smem[];
    float* slog = reinterpret_cast<float*>(smem);

    const int bh = blockIdx.y;              // 0..511
    const int b = bh >> 3, h = bh & 7;
    const __half* A  = qkvh + (size_t)b * 236 * 2304 + h * 96;        // Q
    const __half* Bk = A + 768;                                        // K
    const int bm = blockIdx.x * 128;

    const int tid = threadIdx.x, lane = tid & 31, wid = tid >> 5;
    const int wm = wid & 1, wn = wid >> 1;   // warp m (x64), warp n (x64)
    const int q = lane >> 2, r = lane & 3;
    const uint32_t sbase = smem_u32(smem);

    const int lt = lane >> 3, li = lane & 7;
    const int aRow = wm * 64 + (lt & 1) * 8 + li;
    const int aCol = (lt >> 1) * 16;
    const int bRow = wn * 64 + (lt >> 1) * 8 + li;
    const int bCol = (lt & 1) * 16;

    float acc[4][8][4];
#pragma unroll
    for (int mt = 0; mt < 4; mt++)
#pragma unroll
        for (int j = 0; j < 8; j++)
#pragma unroll
            for (int u = 0; u < 4; u++) acc[mt][j][u] = 0.0f;

    auto issue = [&](int stage, int t) {
        const int k0 = t * 32;
#pragma unroll
        for (int i = 0; i < 2; i++) {   // A: 128 rows x 4 chunks
            int cid = tid + i * 256;
            int m = cid >> 2, c8 = cid & 3;
            int gr = bm + m;
            bool p = (gr < 236);
            const __half* src = p ? (A + (size_t)gr * 2304 + k0 + c8 * 8) : A;
            cpa16(sbase + (uint32_t)(stage * 30720 + m * 80 + c8 * 16), src, p);
        }
#pragma unroll
        for (int i = 0; i < 4; i++) {   // B: 256 rows x 4 chunks
            int cid = tid + i * 256;
            int m = cid >> 2, c8 = cid & 3;
            bool p = (m < 236);
            const __half* src = p ? (Bk + (size_t)m * 2304 + k0 + c8 * 8) : Bk;
            cpa16(sbase + (uint32_t)(stage * 30720 + 10240 + m * 80 + c8 * 16), src, p);
        }
    };

    auto compute = [&](int stage) {
        const uint32_t baseA = sbase + stage * 30720;
        const uint32_t baseB = baseA + 10240;
#pragma unroll
        for (int ks = 0; ks < 32; ks += 16) {
            uint32_t a[4][4], b[4][4];
#pragma unroll
            for (int mt = 0; mt < 4; mt++)
                LDMX4(a[mt], baseA + (uint32_t)((aRow + mt * 16) * 80 + aCol + ks * 2));
#pragma unroll
            for (int jp = 0; jp < 4; jp++)
                LDMX4(b[jp], baseB + (uint32_t)((bRow + jp * 16) * 80 + bCol + ks * 2));
#pragma unroll
            for (int mt = 0; mt < 4; mt++)
#pragma unroll
                for (int j = 0; j < 8; j++) {
                    uint32_t bb2[2] = { b[j >> 1][(j & 1) * 2], b[j >> 1][(j & 1) * 2 + 1] };
                    mma_f16(acc[mt][j], a[mt], bb2);
                }
        }
    };

    // K = 96 -> 3 k-tiles; 4 stages
#pragma unroll
    for (int p = 0; p < 3; p++) {
        issue(p, p);
        asm volatile("cp.async.commit_group;" ::: "memory");
    }
#pragma unroll
    for (int t = 0; t < 3; t++) {
        asm volatile("cp.async.wait_group 2;" ::: "memory");
        __syncthreads();
        asm volatile("cp.async.commit_group;" ::: "memory");   // keep count moving
        compute(t & 3);
    }

    __syncthreads();   // all smem stage reads done; reuse smem for logits

    // dump scaled logits to smem: slog[row][col], pitch 257
#pragma unroll
    for (int mt = 0; mt < 4; mt++) {
#pragma unroll
        for (int j = 0; j < 8; j++) {
            int col = wn * 64 + j * 8 + r * 2;
            int row0 = wm * 64 + mt * 16 + q;
            slog[row0 * 257 + col]           = acc[mt][j][0] * scale;
            slog[row0 * 257 + col + 1]       = acc[mt][j][1] * scale;
            slog[(row0 + 8) * 257 + col]     = acc[mt][j][2] * scale;
            slog[(row0 + 8) * 257 + col + 1] = acc[mt][j][3] * scale;
        }
    }
    __syncthreads();

    // per-row edits + softmax: warp w handles rows w*16 .. w*16+15
    for (int i = 0; i < 16; i++) {
        int row = wid * 16 + i;
        int gr = bm + row;
        if (gr >= 236) break;          // uniform within warp
        float vals[8];
        float mx = -1e30f;
#pragma unroll
        for (int it = 0; it < 8; it++) {
            int c = lane + it * 32;
            float v = -1e30f;
            if (c < 236) {
                if (gr < 196) {
                    if (c >= 216)      v = slog[row * 257 + c - 20];   // PRE-bias copy
                    else if (c >= 196) v = slog[row * 257 + c] - 100.0f;
                    else               v = slog[row * 257 + c];
                } else if (gr < 216) {
                    v = slog[row * 257 + c] - ((c >= 216) ? 100.0f : 0.0f);
                } else {
                    v = slog[row * 257 + c] - ((c >= 196 && c < 216) ? 100.0f : 0.0f);
                }
            }
            vals[it] = v;
            mx = fmaxf(mx, v);
        }
#pragma unroll
        for (int o = 16; o > 0; o >>= 1) mx = fmaxf(mx, __shfl_xor_sync(0xffffffffu, mx, o));
        float s = 0.f;
#pragma unroll
        for (int it = 0; it < 8; it++) { vals[it] = expf(vals[it] - mx); s += vals[it]; }
#pragma unroll
        for (int o = 16; o > 0; o >>= 1) s += __shfl_xor_sync(0xffffffffu, s, o);

        __half* prow = P + ((size_t)bh * 236 + gr) * 240;
#pragma unroll
        for (int it = 0; it < 8; it++) {
            int c = lane + it * 32;
            if (c < 240)
                prow[c] = (c < 236) ? __float2half_rn(vals[it] / s) : __float2half_rn(0.f);
        }
    }
}

// ---------------------------------------------------------------------------
// fp32 -> fp16 conversion (4 floats / thread)
// ---------------------------------------------------------------------------
__global__ void cvt_h(const float* __restrict__ in, __half* __restrict__ out, int n4)
{
    int i = blockIdx.x * blockDim.x + threadIdx.x;
    if (i < n4) {
        float4 v = reinterpret_cast<const float4*>(in)[i];
        uint2 u;
        __half2 h0 = __floats2half2_rn(v.x, v.y);
        __half2 h1 = __floats2half2_rn(v.z, v.w);
        u.x = *reinterpret_cast<uint32_t*>(&h0);
        u.y = *reinterpret_cast<uint32_t*>(&h1);
        reinterpret_cast<uint2*>(out)[i] = u;
    }
}

// ---------------------------------------------------------------------------
// V transpose fp16: vth[bh][d][tok] = qkvh[(b*236+tok)*2304 + 1536 + h*96 + d]
// Output pitch 240 (tok 236..239 zero-filled).
// ---------------------------------------------------------------------------
__global__ void vtrans_kernel(const __half* __restrict__ qkvh, __half* __restrict__ vt)
{
    __shared__ float t[32][33];
    const int bh = blockIdx.z;
    const int b = bh >> 3, h = bh & 7;
    const int t0 = blockIdx.x * 32;
    const int d0 = blockIdx.y * 32;
    const int tx = threadIdx.x, ty = threadIdx.y;

#pragma unroll
    for (int r = ty; r < 32; r += 8) {
        int tok = t0 + r;
        int d = d0 + tx;
        float v = 0.f;
        if (tok < 236)
            v = __half2float(qkvh[(size_t)(b * 236 + tok) * 2304 + 1536 + h * 96 + d]);
        t[r][tx] = v;
    }
    __syncthreads();
#pragma unroll
    for (int r = ty; r < 32; r += 8) {
        int d = d0 + r;
        int tok = t0 + tx;
        if (tok < 240)
            vt[((size_t)bh * 96 + d) * 240 + tok] =
                (tok < 236) ? __float2half_rn(t[tx][r]) : __float2half_rn(0.f);
    }
}

// ---------------------------------------------------------------------------
extern "C" void kernel_launch(void* const* d_in, const int* in_sizes, int n_in,
                              void* d_out, int out_size)
{
    const float* x      = (const float*)d_in[0];   // [64,236,768]
    const float* qkv_w  = (const float*)d_in[1];   // [2304,768]
    const float* proj_w = (const float*)d_in[2];   // [768,768]
    const float* proj_b = (const float*)d_in[3];   // [768]
    float* out = (float*)d_out;                    // [64,236,768]

    __half *qkvh, *P, *vth, *atth, *xh, *wh, *pwh;
    cudaGetSymbolAddress((void**)&qkvh, g_qkvh);
    cudaGetSymbolAddress((void**)&P,    g_P);
    cudaGetSymbolAddress((void**)&vth,  g_vth);
    cudaGetSymbolAddress((void**)&atth, g_atth);
    cudaGetSymbolAddress((void**)&xh,   g_xh);
    cudaGetSymbolAddress((void**)&wh,   g_wh);
    cudaGetSymbolAddress((void**)&pwh,  g_pwh);

    const int SMEM = 81920;        // hgemm: 4 stages x 20480 B
    const int SMEM_QK = 131584;    // qk_softmax: max(122880, 128*257*4)
    cudaFuncSetAttribute(hgemm<true,  false>, cudaFuncAttributeMaxDynamicSharedMemorySize, SMEM);
    cudaFuncSetAttribute(hgemm<false, true>,  cudaFuncAttributeMaxDynamicSharedMemorySize, SMEM);
    cudaFuncSetAttribute(qk_softmax, cudaFuncAttributeMaxDynamicSharedMemorySize, SMEM_QK);

    const float scale = 0.10206207261596575f;      // 1/sqrt(96)

    // 0) convert inputs to fp16
    cvt_h<<<(15104 * 768 / 4 + 255) / 256, 256>>>(x, xh, 15104 * 768 / 4);
    cvt_h<<<(2304 * 768 / 4 + 255) / 256, 256>>>(qkv_w, wh, 2304 * 768 / 4);
    cvt_h<<<(768 * 768 / 4 + 255) / 256, 256>>>(proj_w, pwh, 768 * 768 / 4);

    // 1) qkvh = x @ qkv_w^T            [15104 x 2304], K=768, fp16 out
    hgemm<true, false><<<dim3(118, 18, 1), 256, SMEM>>>(
        xh, wh, nullptr, qkvh,
        15104, 2304, 768, 768, 768, 2304,
        1, 0, 0, 0, 0, 0, 0, 1.0f);

    // 2) fused QK^T*scale + edits + softmax -> P fp16 (padded 240)
    qk_softmax<<<dim3(2, 512), 256, SMEM_QK>>>(qkvh, P, scale);

    // 3) V transpose -> vth fp16 (padded to 240)
    vtrans_kernel<<<dim3(8, 3, 512), dim3(32, 8)>>>(qkvh, vth);

    // 4) atth[bh] = P @ vth^T          512 batches, 236x96, K=240, fp16 out
    hgemm<true, false><<<dim3(2, 1, 512), 256, SMEM>>>(
        P, vth, nullptr, atth,
        236, 96, 240, 240, 240, 768,
        8, (long)8 * 236 * 240, (long)236 * 240,
        (long)8 * 96 * 240, (long)96 * 240,
        (long)236 * 768, 96,
        1.0f);

    // 5) out = atth @ proj_w^T + proj_b  [15104 x 768], K=768, fp32 out + bias
    hgemm<false, true><<<dim3(118, 6, 1), 256, SMEM>>>(
        atth, pwh, proj_b, out,
        15104, 768, 768, 768, 768, 768,
        1, 0, 0, 0, 0, 0, 0, 1.0f);
}

// round 15
// speedup vs baseline: 1.6165x; 1.2640x over previous
#include <cuda_runtime.h>
#include <cuda_fp16.h>
#include <cstdint>
#include <math.h>

// ---------------------------------------------------------------------------
// Problem: B=64, N=236, C=768, H=8, D=96.  M = B*N = 15104 = 118*128.
// Scratch (static device globals -- no runtime allocation allowed)
// ---------------------------------------------------------------------------
__device__ __half g_qkvh[(size_t)15104 * 2304];  // [B*N, 3C] fp16
__device__ __half g_P[(size_t)512 * 236 * 240];  // probs fp16, K-padded to 240
__device__ __half g_vth[(size_t)512 * 96 * 240]; // V^T fp16, padded to 240
__device__ __half g_atth[(size_t)15104 * 768];   // attention out fp16
__device__ __half g_xh[(size_t)15104 * 768];     // x fp16
__device__ __half g_wh[(size_t)2304 * 768];      // qkv_w fp16
__device__ __half g_pwh[(size_t)768 * 768];      // proj_w fp16

// ---------------------------------------------------------------------------
__device__ __forceinline__ uint32_t smem_u32(const void* p) {
    uint32_t a;
    asm("{ .reg .u64 t; cvta.to.shared.u64 t, %1; cvt.u32.u64 %0, t; }" : "=r"(a) : "l"(p));
    return a;
}
__device__ __forceinline__ void mma_f16(float* c, const uint32_t* a, const uint32_t* b) {
    asm volatile(
        "mma.sync.aligned.m16n8k16.row.col.f32.f16.f16.f32 "
        "{%0,%1,%2,%3}, {%4,%5,%6,%7}, {%8,%9}, {%0,%1,%2,%3};"
        : "+f"(c[0]), "+f"(c[1]), "+f"(c[2]), "+f"(c[3])
        : "r"(a[0]), "r"(a[1]), "r"(a[2]), "r"(a[3]), "r"(b[0]), "r"(b[1]));
}
#define LDMX4(r, addr) \
    asm volatile("ldmatrix.sync.aligned.m8n8.x4.shared.b16 {%0,%1,%2,%3}, [%4];" \
                 : "=r"((r)[0]), "=r"((r)[1]), "=r"((r)[2]), "=r"((r)[3]) : "r"(addr))
// cp.async 16B; when !pred copies 0 source bytes -> dst 16B zero-filled
__device__ __forceinline__ void cpa16(uint32_t dst, const void* src, bool pred) {
    int sz = pred ? 16 : 0;
    asm volatile("cp.async.cg.shared.global [%0], [%1], 16, %2;"
                 :: "r"(dst), "l"(src), "r"(sz) : "memory");
}

// ---------------------------------------------------------------------------
// fp16 tensor-core batched NT GEMM (R12/R14 engine -- best measured config):
// C[m,n] = alpha*sum_k A[m,k]*B[n,k] (+bias[n]); fp32 accum; C fp32/fp16.
// 128x128x32 tile, 256 threads, 8 warps (4x2), warp tile 32x64,
// 4-stage cp.async pipeline, one __syncthreads per k-tile, ldmatrix loads.
// ---------------------------------------------------------------------------
template<bool OUT_HALF, bool ADD_BIAS>
__global__ void __launch_bounds__(256, 2)
hgemm(const __half* __restrict__ Ag, const __half* __restrict__ Bg,
      const float* __restrict__ bias, void* __restrict__ Cv,
      int M, int N, int K, int lda, int ldb, int ldc,
      int HB, long sAb, long sAh, long sBb, long sBh, long sCb, long sCh,
      float alpha)
{
    extern __shared__ __half smem[];

    const int z  = blockIdx.z;
    const int hb = z % HB, bb = z / HB;
    const __half* A = Ag + (size_t)bb * sAb + (size_t)hb * sAh;
    const __half* B = Bg + (size_t)bb * sBb + (size_t)hb * sBh;

    const int bm = blockIdx.x * 128, bn = blockIdx.y * 128;
    const int tid = threadIdx.x, lane = tid & 31, wid = tid >> 5;
    const int wr = wid & 3, wc = wid >> 2;
    const int q = lane >> 2, r = lane & 3;
    const uint32_t sbase = smem_u32(smem);

    const int lt = lane >> 3, li = lane & 7;
    const int aRow = wr * 32 + (lt & 1) * 8 + li;
    const int aCol = (lt >> 1) * 16;
    const int bRow = wc * 64 + (lt >> 1) * 8 + li;
    const int bCol = (lt & 1) * 16;

    float acc[2][8][4];
#pragma unroll
    for (int t2 = 0; t2 < 2; t2++)
#pragma unroll
        for (int j = 0; j < 8; j++)
#pragma unroll
            for (int u = 0; u < 4; u++) acc[t2][j][u] = 0.0f;

    auto issue = [&](int stage, int t) {
        const int k0 = t * 32;
#pragma unroll
        for (int i = 0; i < 2; i++) {   // A
            int cid = tid + i * 256;
            int m = cid >> 2, c8 = cid & 3;
            int gc = k0 + c8 * 8;
            int gr = bm + m;
            bool p = (gr < M) && (gc + 8 <= K);
            const __half* src = p ? (A + (size_t)gr * lda + gc) : A;
            cpa16(sbase + (uint32_t)(stage * 20480 + m * 80 + c8 * 16), src, p);
        }
#pragma unroll
        for (int i = 0; i < 2; i++) {   // B
            int cid = tid + i * 256;
            int m = cid >> 2, c8 = cid & 3;
            int gc = k0 + c8 * 8;
            int gr = bn + m;
            bool p = (gr < N) && (gc + 8 <= K);
            const __half* src = p ? (B + (size_t)gr * ldb + gc) : B;
            cpa16(sbase + (uint32_t)(stage * 20480 + 10240 + m * 80 + c8 * 16), src, p);
        }
    };

    auto compute = [&](int stage) {
        const uint32_t baseA = sbase + stage * 20480;
        const uint32_t baseB = baseA + 10240;
#pragma unroll
        for (int ks = 0; ks < 32; ks += 16) {
            uint32_t a[2][4], b[4][4];
#pragma unroll
            for (int t2 = 0; t2 < 2; t2++)
                LDMX4(a[t2], baseA + (uint32_t)((aRow + t2 * 16) * 80 + aCol + ks * 2));
#pragma unroll
            for (int jp = 0; jp < 4; jp++)
                LDMX4(b[jp], baseB + (uint32_t)((bRow + jp * 16) * 80 + bCol + ks * 2));
#pragma unroll
            for (int t2 = 0; t2 < 2; t2++)
#pragma unroll
                for (int j = 0; j < 8; j++) {
                    uint32_t bb2[2] = { b[j >> 1][(j & 1) * 2], b[j >> 1][(j & 1) * 2 + 1] };
                    mma_f16(acc[t2][j], a[t2], bb2);
                }
        }
    };

    const int ntiles = (K + 31) / 32;

#pragma unroll
    for (int p = 0; p < 3; p++) {
        if (p < ntiles) issue(p, p);
        asm volatile("cp.async.commit_group;" ::: "memory");
    }

    for (int t = 0; t < ntiles; t++) {
        asm volatile("cp.async.wait_group 2;" ::: "memory");
        __syncthreads();
        if (t + 3 < ntiles) issue((t + 3) & 3, t + 3);
        asm volatile("cp.async.commit_group;" ::: "memory");
        compute(t & 3);
    }

#pragma unroll
    for (int t2 = 0; t2 < 2; t2++) {
#pragma unroll
        for (int j = 0; j < 8; j++) {
            int col = bn + wc * 64 + j * 8 + r * 2;
            if (col >= N) continue;
            int row0 = bm + wr * 32 + t2 * 16 + q;
            float bx = 0.f, by = 0.f;
            if (ADD_BIAS) { bx = bias[col]; by = bias[col + 1]; }
#pragma unroll
            for (int h = 0; h < 2; h++) {
                int row = row0 + h * 8;
                if (row >= M) continue;
                float vx = acc[t2][j][h * 2 + 0] * alpha + bx;
                float vy = acc[t2][j][h * 2 + 1] * alpha + by;
                if (OUT_HALF) {
                    __half2* dst = reinterpret_cast<__half2*>(
                        (__half*)Cv + (size_t)bb * sCb + (size_t)hb * sCh + (size_t)row * ldc + col);
                    *dst = __floats2half2_rn(vx, vy);
                } else {
                    float2* dst = reinterpret_cast<float2*>(
                        (float*)Cv + (size_t)bb * sCb + (size_t)hb * sCh + (size_t)row * ldc + col);
                    *dst = make_float2(vx, vy);
                }
            }
        }
    }
}

// ---------------------------------------------------------------------------
// Fused QK^T*scale + block edits + softmax -> P fp16 (register-resident).
// 512 threads (16 warps: 4m x 4n), CTA tile 128x256x32, warp tile 32x64.
// K=96 = exactly 3 k-tiles, all prefetched into 3 cp.async stages (92160 B).
// Edits: cols 192-255 live entirely in n-warp wn==3; the [216,236)<-[196,216)
// copy is shfl_xor(.,2): src lane r^2, src register j-3 (r<2) / j-2 (r>=2).
// Row softmax: xor-shuffle within q-group + red[128][4] cross-warp exchange.
// ---------------------------------------------------------------------------
__global__ void __launch_bounds__(512, 1)
qk_softmax(const __half* __restrict__ qkvh, __half* __restrict__ P, float scale)
{
    extern __shared__ __half smem[];
    __shared__ float red[128][4];

    const int bh = blockIdx.y;              // 0..511
    const int b = bh >> 3, h = bh & 7;
    const __half* A  = qkvh + (size_t)b * 236 * 2304 + h * 96;        // Q
    const __half* Bk = A + 768;                                        // K
    const int bm = blockIdx.x * 128;

    const int tid = threadIdx.x, lane = tid & 31, wid = tid >> 5;
    const int wm = wid & 3, wn = wid >> 2;   // 4 m-warps x32, 4 n-warps x64
    const int q = lane >> 2, r = lane & 3;
    const uint32_t sbase = smem_u32(smem);

    const int lt = lane >> 3, li = lane & 7;
    const int aRow = wm * 32 + (lt & 1) * 8 + li;
    const int aCol = (lt >> 1) * 16;
    const int bRow = wn * 64 + (lt >> 1) * 8 + li;
    const int bCol = (lt & 1) * 16;

    float acc[2][8][4];
#pragma unroll
    for (int mt = 0; mt < 2; mt++)
#pragma unroll
        for (int j = 0; j < 8; j++)
#pragma unroll
            for (int u = 0; u < 4; u++) acc[mt][j][u] = 0.0f;

    auto issue = [&](int stage, int t) {
        const int k0 = t * 32;
        {   // A: 128 rows x 4 chunks = 512, one per thread
            int m = tid >> 2, c8 = tid & 3;
            int gr = bm + m;
            bool p = (gr < 236);
            const __half* src = p ? (A + (size_t)gr * 2304 + k0 + c8 * 8) : A;
            cpa16(sbase + (uint32_t)(stage * 30720 + m * 80 + c8 * 16), src, p);
        }
#pragma unroll
        for (int i = 0; i < 2; i++) {   // B: 256 rows x 4 chunks = 1024
            int cid = tid + i * 512;
            int m = cid >> 2, c8 = cid & 3;
            bool p = (m < 236);
            const __half* src = p ? (Bk + (size_t)m * 2304 + k0 + c8 * 8) : Bk;
            cpa16(sbase + (uint32_t)(stage * 30720 + 10240 + m * 80 + c8 * 16), src, p);
        }
    };

    auto compute = [&](int stage) {
        const uint32_t baseA = sbase + stage * 30720;
        const uint32_t baseB = baseA + 10240;
#pragma unroll
        for (int ks = 0; ks < 32; ks += 16) {
            uint32_t a[2][4], b[4][4];
#pragma unroll
            for (int mt = 0; mt < 2; mt++)
                LDMX4(a[mt], baseA + (uint32_t)((aRow + mt * 16) * 80 + aCol + ks * 2));
#pragma unroll
            for (int jp = 0; jp < 4; jp++)
                LDMX4(b[jp], baseB + (uint32_t)((bRow + jp * 16) * 80 + bCol + ks * 2));
#pragma unroll
            for (int mt = 0; mt < 2; mt++)
#pragma unroll
                for (int j = 0; j < 8; j++) {
                    uint32_t bb2[2] = { b[j >> 1][(j & 1) * 2], b[j >> 1][(j & 1) * 2 + 1] };
                    mma_f16(acc[mt][j], a[mt], bb2);
                }
        }
    };

    // K=96: 3 tiles fully prefetched, no refill
#pragma unroll
    for (int p = 0; p < 3; p++) {
        issue(p, p);
        asm volatile("cp.async.commit_group;" ::: "memory");
    }
    asm volatile("cp.async.wait_group 2;" ::: "memory"); __syncthreads(); compute(0);
    asm volatile("cp.async.wait_group 1;" ::: "memory"); __syncthreads(); compute(1);
    asm volatile("cp.async.wait_group 0;" ::: "memory"); __syncthreads(); compute(2);

    // scale all logits
#pragma unroll
    for (int mt = 0; mt < 2; mt++)
#pragma unroll
        for (int j = 0; j < 8; j++)
#pragma unroll
            for (int u = 0; u < 4; u++) acc[mt][j][u] *= scale;

    // ---- block edits (entirely inside wn==3: cols 192..255) ----
    if (wn == 3) {
#pragma unroll
        for (int mt = 0; mt < 2; mt++) {
#pragma unroll
            for (int j = 3; j <= 5; j++) {
                // value this lane must SEND to its xor-2 partner:
                //   partner r>=2 needs src reg j-2; partner r<2 needs src reg j-3
                float tmp[4];
#pragma unroll
                for (int u = 0; u < 4; u++) {
                    float x = (r < 2) ? acc[mt][j - 2][u] : acc[mt][j - 3][u];
                    tmp[u] = __shfl_xor_sync(0xffffffffu, x, 2);
                }
                int o = j * 8 + r * 2;            // col offset within warp (192+o)
#pragma unroll
                for (int u = 0; u < 4; u++) {
                    int gr = bm + wm * 32 + mt * 16 + q + (u >= 2 ? 8 : 0);
                    if (gr < 196 && o >= 24 && o < 44)
                        acc[mt][j][u] = tmp[u];   // copy uses PRE-bias values
                }
            }
            // bias subtractions
#pragma unroll
            for (int j = 0; j < 8; j++) {
                int col = 192 + j * 8 + r * 2;    // even col; col+1 same region
#pragma unroll
                for (int u = 0; u < 4; u++) {
                    int gr = bm + wm * 32 + mt * 16 + q + (u >= 2 ? 8 : 0);
                    bool sub;
                    if (gr < 196)       sub = (col >= 196 && col < 216);
                    else if (gr < 216)  sub = (col >= 216 && col < 236);
                    else                sub = (col >= 196 && col < 216);
                    if (sub) acc[mt][j][u] -= 100.0f;
                }
            }
        }
    }

    // ---- row softmax ----
    // local max per row (mt, half)
    float mx[2][2], sm[2][2];
#pragma unroll
    for (int mt = 0; mt < 2; mt++)
#pragma unroll
        for (int hf = 0; hf < 2; hf++) {
            float m = -1e30f;
#pragma unroll
            for (int j = 0; j < 8; j++) {
                int o = j * 8 + r * 2;
                bool valid = (wn < 3) || (o < 44);
                if (valid) {
                    m = fmaxf(m, acc[mt][j][hf * 2 + 0]);
                    m = fmaxf(m, acc[mt][j][hf * 2 + 1]);
                }
            }
            m = fmaxf(m, __shfl_xor_sync(0xffffffffu, m, 1));
            m = fmaxf(m, __shfl_xor_sync(0xffffffffu, m, 2));
            mx[mt][hf] = m;
        }
    if (r == 0) {
#pragma unroll
        for (int mt = 0; mt < 2; mt++)
#pragma unroll
            for (int hf = 0; hf < 2; hf++)
                red[wm * 32 + mt * 16 + hf * 8 + q][wn] = mx[mt][hf];
    }
    __syncthreads();
#pragma unroll
    for (int mt = 0; mt < 2; mt++)
#pragma unroll
        for (int hf = 0; hf < 2; hf++) {
            int sr = wm * 32 + mt * 16 + hf * 8 + q;
            mx[mt][hf] = fmaxf(fmaxf(red[sr][0], red[sr][1]),
                               fmaxf(red[sr][2], red[sr][3]));
        }
    __syncthreads();

    // exp + local sum
#pragma unroll
    for (int mt = 0; mt < 2; mt++)
#pragma unroll
        for (int hf = 0; hf < 2; hf++) {
            float s = 0.f;
#pragma unroll
            for (int j = 0; j < 8; j++) {
                int o = j * 8 + r * 2;
                bool valid = (wn < 3) || (o < 44);
                float e0 = 0.f, e1 = 0.f;
                if (valid) {
                    e0 = expf(acc[mt][j][hf * 2 + 0] - mx[mt][hf]);
                    e1 = expf(acc[mt][j][hf * 2 + 1] - mx[mt][hf]);
                }
                acc[mt][j][hf * 2 + 0] = e0;
                acc[mt][j][hf * 2 + 1] = e1;
                s += e0 + e1;
            }
            s += __shfl_xor_sync(0xffffffffu, s, 1);
            s += __shfl_xor_sync(0xffffffffu, s, 2);
            sm[mt][hf] = s;
        }
    if (r == 0) {
#pragma unroll
        for (int mt = 0; mt < 2; mt++)
#pragma unroll
            for (int hf = 0; hf < 2; hf++)
                red[wm * 32 + mt * 16 + hf * 8 + q][wn] = sm[mt][hf];
    }
    __syncthreads();
#pragma unroll
    for (int mt = 0; mt < 2; mt++)
#pragma unroll
        for (int hf = 0; hf < 2; hf++) {
            int sr = wm * 32 + mt * 16 + hf * 8 + q;
            sm[mt][hf] = red[sr][0] + red[sr][1] + red[sr][2] + red[sr][3];
        }

    // write P fp16 (pitch 240; cols 236..239 zero)
#pragma unroll
    for (int mt = 0; mt < 2; mt++)
#pragma unroll
        for (int hf = 0; hf < 2; hf++) {
            int gr = bm + wm * 32 + mt * 16 + hf * 8 + q;
            if (gr >= 236) continue;
            __half* prow = P + ((size_t)bh * 236 + gr) * 240;
            float inv = 1.0f / sm[mt][hf];
#pragma unroll
            for (int j = 0; j < 8; j++) {
                int col = wn * 64 + j * 8 + r * 2;
                if (col >= 240) continue;
                float v0 = 0.f, v1 = 0.f;
                if (col < 236) {
                    v0 = acc[mt][j][hf * 2 + 0] * inv;
                    v1 = acc[mt][j][hf * 2 + 1] * inv;
                }
                *reinterpret_cast<__half2*>(prow + col) = __floats2half2_rn(v0, v1);
            }
        }
}

// ---------------------------------------------------------------------------
// fp32 -> fp16 conversion (4 floats / thread)
// ---------------------------------------------------------------------------
__global__ void cvt_h(const float* __restrict__ in, __half* __restrict__ out, int n4)
{
    int i = blockIdx.x * blockDim.x + threadIdx.x;
    if (i < n4) {
        float4 v = reinterpret_cast<const float4*>(in)[i];
        uint2 u;
        __half2 h0 = __floats2half2_rn(v.x, v.y);
        __half2 h1 = __floats2half2_rn(v.z, v.w);
        u.x = *reinterpret_cast<uint32_t*>(&h0);
        u.y = *reinterpret_cast<uint32_t*>(&h1);
        reinterpret_cast<uint2*>(out)[i] = u;
    }
}

// ---------------------------------------------------------------------------
// V transpose fp16: vth[bh][d][tok] = qkvh[(b*236+tok)*2304 + 1536 + h*96 + d]
// Output pitch 240 (tok 236..239 zero-filled).
// ---------------------------------------------------------------------------
__global__ void vtrans_kernel(const __half* __restrict__ qkvh, __half* __restrict__ vt)
{
    __shared__ float t[32][33];
    const int bh = blockIdx.z;
    const int b = bh >> 3, h = bh & 7;
    const int t0 = blockIdx.x * 32;
    const int d0 = blockIdx.y * 32;
    const int tx = threadIdx.x, ty = threadIdx.y;

#pragma unroll
    for (int r = ty; r < 32; r += 8) {
        int tok = t0 + r;
        int d = d0 + tx;
        float v = 0.f;
        if (tok < 236)
            v = __half2float(qkvh[(size_t)(b * 236 + tok) * 2304 + 1536 + h * 96 + d]);
        t[r][tx] = v;
    }
    __syncthreads();
#pragma unroll
    for (int r = ty; r < 32; r += 8) {
        int d = d0 + r;
        int tok = t0 + tx;
        if (tok < 240)
            vt[((size_t)bh * 96 + d) * 240 + tok] =
                (tok < 236) ? __float2half_rn(t[tx][r]) : __float2half_rn(0.f);
    }
}

// ---------------------------------------------------------------------------
extern "C" void kernel_launch(void* const* d_in, const int* in_sizes, int n_in,
                              void* d_out, int out_size)
{
    const float* x      = (const float*)d_in[0];   // [64,236,768]
    const float* qkv_w  = (const float*)d_in[1];   // [2304,768]
    const float* proj_w = (const float*)d_in[2];   // [768,768]
    const float* proj_b = (const float*)d_in[3];   // [768]
    float* out = (float*)d_out;                    // [64,236,768]

    __half *qkvh, *P, *vth, *atth, *xh, *wh, *pwh;
    cudaGetSymbolAddress((void**)&qkvh, g_qkvh);
    cudaGetSymbolAddress((void**)&P,    g_P);
    cudaGetSymbolAddress((void**)&vth,  g_vth);
    cudaGetSymbolAddress((void**)&atth, g_atth);
    cudaGetSymbolAddress((void**)&xh,   g_xh);
    cudaGetSymbolAddress((void**)&wh,   g_wh);
    cudaGetSymbolAddress((void**)&pwh,  g_pwh);

    const int SMEM = 81920;        // hgemm: 4 stages x 20480 B
    const int SMEM_QK = 92160;     // qk_softmax: 3 stages x 30720 B
    cudaFuncSetAttribute(hgemm<true,  false>, cudaFuncAttributeMaxDynamicSharedMemorySize, SMEM);
    cudaFuncSetAttribute(hgemm<false, true>,  cudaFuncAttributeMaxDynamicSharedMemorySize, SMEM);
    cudaFuncSetAttribute(qk_softmax, cudaFuncAttributeMaxDynamicSharedMemorySize, SMEM_QK);

    const float scale = 0.10206207261596575f;      // 1/sqrt(96)

    // 0) convert inputs to fp16
    cvt_h<<<(15104 * 768 / 4 + 255) / 256, 256>>>(x, xh, 15104 * 768 / 4);
    cvt_h<<<(2304 * 768 / 4 + 255) / 256, 256>>>(qkv_w, wh, 2304 * 768 / 4);
    cvt_h<<<(768 * 768 / 4 + 255) / 256, 256>>>(proj_w, pwh, 768 * 768 / 4);

    // 1) qkvh = x @ qkv_w^T            [15104 x 2304], K=768, fp16 out
    hgemm<true, false><<<dim3(118, 18, 1), 256, SMEM>>>(
        xh, wh, nullptr, qkvh,
        15104, 2304, 768, 768, 768, 2304,
        1, 0, 0, 0, 0, 0, 0, 1.0f);

    // 2) fused QK^T*scale + edits + softmax -> P fp16 (padded 240)
    qk_softmax<<<dim3(2, 512), 512, SMEM_QK>>>(qkvh, P, scale);

    // 3) V transpose -> vth fp16 (padded to 240)
    vtrans_kernel<<<dim3(8, 3, 512), dim3(32, 8)>>>(qkvh, vth);

    // 4) atth[bh] = P @ vth^T          512 batches, 236x96, K=240, fp16 out
    hgemm<true, false><<<dim3(2, 1, 512), 256, SMEM>>>(
        P, vth, nullptr, atth,
        236, 96, 240, 240, 240, 768,
        8, (long)8 * 236 * 240, (long)236 * 240,
        (long)8 * 96 * 240, (long)96 * 240,
        (long)236 * 768, 96,
        1.0f);

    // 5) out = atth @ proj_w^T + proj_b  [15104 x 768], K=768, fp32 out + bias
    hgemm<false, true><<<dim3(118, 6, 1), 256, SMEM>>>(
        atth, pwh, proj_b, out,
        15104, 768, 768, 768, 768, 768,
        1, 0, 0, 0, 0, 0, 0, 1.0f);
}

// round 16
// speedup vs baseline: 1.7672x; 1.0932x over previous
#include <cuda_runtime.h>
#include <cuda_fp16.h>
#include <cstdint>
#include <math.h>

// ---------------------------------------------------------------------------
// Problem: B=64, N=236, C=768, H=8, D=96.  M = B*N = 15104 = 118*128.
// Scratch (static device globals -- no runtime allocation allowed)
// ---------------------------------------------------------------------------
__device__ __half g_qkvh[(size_t)15104 * 2304];  // [B*N, 3C] fp16
__device__ __half g_P[(size_t)512 * 236 * 240];  // probs fp16, K-padded to 240
__device__ __half g_atth[(size_t)15104 * 768];   // attention out fp16
__device__ __half g_xh[(size_t)15104 * 768];     // x fp16
__device__ __half g_wh[(size_t)2304 * 768];      // qkv_w fp16
__device__ __half g_pwh[(size_t)768 * 768];      // proj_w fp16

// ---------------------------------------------------------------------------
__device__ __forceinline__ uint32_t smem_u32(const void* p) {
    uint32_t a;
    asm("{ .reg .u64 t; cvta.to.shared.u64 t, %1; cvt.u32.u64 %0, t; }" : "=r"(a) : "l"(p));
    return a;
}
__device__ __forceinline__ void mma_f16(float* c, const uint32_t* a, const uint32_t* b) {
    asm volatile(
        "mma.sync.aligned.m16n8k16.row.col.f32.f16.f16.f32 "
        "{%0,%1,%2,%3}, {%4,%5,%6,%7}, {%8,%9}, {%0,%1,%2,%3};"
        : "+f"(c[0]), "+f"(c[1]), "+f"(c[2]), "+f"(c[3])
        : "r"(a[0]), "r"(a[1]), "r"(a[2]), "r"(a[3]), "r"(b[0]), "r"(b[1]));
}
#define LDMX4(r, addr) \
    asm volatile("ldmatrix.sync.aligned.m8n8.x4.shared.b16 {%0,%1,%2,%3}, [%4];" \
                 : "=r"((r)[0]), "=r"((r)[1]), "=r"((r)[2]), "=r"((r)[3]) : "r"(addr))
#define LDMX4T(r, addr) \
    asm volatile("ldmatrix.sync.aligned.m8n8.x4.trans.shared.b16 {%0,%1,%2,%3}, [%4];" \
                 : "=r"((r)[0]), "=r"((r)[1]), "=r"((r)[2]), "=r"((r)[3]) : "r"(addr))
// cp.async 16B; when !pred copies 0 source bytes -> dst 16B zero-filled
__device__ __forceinline__ void cpa16(uint32_t dst, const void* src, bool pred) {
    int sz = pred ? 16 : 0;
    asm volatile("cp.async.cg.shared.global [%0], [%1], 16, %2;"
                 :: "r"(dst), "l"(src), "r"(sz) : "memory");
}

// ---------------------------------------------------------------------------
// fp16 tensor-core batched NT GEMM (best measured config, R12/R14/R15):
// C[m,n] = alpha*sum_k A[m,k]*B[n,k] (+bias[n]); fp32 accum; C fp32/fp16.
// 128x128x32 tile, 256 threads, 8 warps (4x2), warp tile 32x64,
// 4-stage cp.async pipeline, one __syncthreads per k-tile, ldmatrix loads.
// ---------------------------------------------------------------------------
template<bool OUT_HALF, bool ADD_BIAS>
__global__ void __launch_bounds__(256, 2)
hgemm(const __half* __restrict__ Ag, const __half* __restrict__ Bg,
      const float* __restrict__ bias, void* __restrict__ Cv,
      int M, int N, int K, int lda, int ldb, int ldc,
      int HB, long sAb, long sAh, long sBb, long sBh, long sCb, long sCh,
      float alpha)
{
    extern __shared__ __half smem[];

    const int z  = blockIdx.z;
    const int hb = z % HB, bb = z / HB;
    const __half* A = Ag + (size_t)bb * sAb + (size_t)hb * sAh;
    const __half* B = Bg + (size_t)bb * sBb + (size_t)hb * sBh;

    const int bm = blockIdx.x * 128, bn = blockIdx.y * 128;
    const int tid = threadIdx.x, lane = tid & 31, wid = tid >> 5;
    const int wr = wid & 3, wc = wid >> 2;
    const int q = lane >> 2, r = lane & 3;
    const uint32_t sbase = smem_u32(smem);

    const int lt = lane >> 3, li = lane & 7;
    const int aRow = wr * 32 + (lt & 1) * 8 + li;
    const int aCol = (lt >> 1) * 16;
    const int bRow = wc * 64 + (lt >> 1) * 8 + li;
    const int bCol = (lt & 1) * 16;

    float acc[2][8][4];
#pragma unroll
    for (int t2 = 0; t2 < 2; t2++)
#pragma unroll
        for (int j = 0; j < 8; j++)
#pragma unroll
            for (int u = 0; u < 4; u++) acc[t2][j][u] = 0.0f;

    auto issue = [&](int stage, int t) {
        const int k0 = t * 32;
#pragma unroll
        for (int i = 0; i < 2; i++) {   // A
            int cid = tid + i * 256;
            int m = cid >> 2, c8 = cid & 3;
            int gc = k0 + c8 * 8;
            int gr = bm + m;
            bool p = (gr < M) && (gc + 8 <= K);
            const __half* src = p ? (A + (size_t)gr * lda + gc) : A;
            cpa16(sbase + (uint32_t)(stage * 20480 + m * 80 + c8 * 16), src, p);
        }
#pragma unroll
        for (int i = 0; i < 2; i++) {   // B
            int cid = tid + i * 256;
            int m = cid >> 2, c8 = cid & 3;
            int gc = k0 + c8 * 8;
            int gr = bn + m;
            bool p = (gr < N) && (gc + 8 <= K);
            const __half* src = p ? (B + (size_t)gr * ldb + gc) : B;
            cpa16(sbase + (uint32_t)(stage * 20480 + 10240 + m * 80 + c8 * 16), src, p);
        }
    };

    auto compute = [&](int stage) {
        const uint32_t baseA = sbase + stage * 20480;
        const uint32_t baseB = baseA + 10240;
#pragma unroll
        for (int ks = 0; ks < 32; ks += 16) {
            uint32_t a[2][4], b[4][4];
#pragma unroll
            for (int t2 = 0; t2 < 2; t2++)
                LDMX4(a[t2], baseA + (uint32_t)((aRow + t2 * 16) * 80 + aCol + ks * 2));
#pragma unroll
            for (int jp = 0; jp < 4; jp++)
                LDMX4(b[jp], baseB + (uint32_t)((bRow + jp * 16) * 80 + bCol + ks * 2));
#pragma unroll
            for (int t2 = 0; t2 < 2; t2++)
#pragma unroll
                for (int j = 0; j < 8; j++) {
                    uint32_t bb2[2] = { b[j >> 1][(j & 1) * 2], b[j >> 1][(j & 1) * 2 + 1] };
                    mma_f16(acc[t2][j], a[t2], bb2);
                }
        }
    };

    const int ntiles = (K + 31) / 32;

#pragma unroll
    for (int p = 0; p < 3; p++) {
        if (p < ntiles) issue(p, p);
        asm volatile("cp.async.commit_group;" ::: "memory");
    }

    for (int t = 0; t < ntiles; t++) {
        asm volatile("cp.async.wait_group 2;" ::: "memory");
        __syncthreads();
        if (t + 3 < ntiles) issue((t + 3) & 3, t + 3);
        asm volatile("cp.async.commit_group;" ::: "memory");
        compute(t & 3);
    }

#pragma unroll
    for (int t2 = 0; t2 < 2; t2++) {
#pragma unroll
        for (int j = 0; j < 8; j++) {
            int col = bn + wc * 64 + j * 8 + r * 2;
            if (col >= N) continue;
            int row0 = bm + wr * 32 + t2 * 16 + q;
            float bx = 0.f, by = 0.f;
            if (ADD_BIAS) { bx = bias[col]; by = bias[col + 1]; }
#pragma unroll
            for (int h = 0; h < 2; h++) {
                int row = row0 + h * 8;
                if (row >= M) continue;
                float vx = acc[t2][j][h * 2 + 0] * alpha + bx;
                float vy = acc[t2][j][h * 2 + 1] * alpha + by;
                if (OUT_HALF) {
                    __half2* dst = reinterpret_cast<__half2*>(
                        (__half*)Cv + (size_t)bb * sCb + (size_t)hb * sCh + (size_t)row * ldc + col);
                    *dst = __floats2half2_rn(vx, vy);
                } else {
                    float2* dst = reinterpret_cast<float2*>(
                        (float*)Cv + (size_t)bb * sCb + (size_t)hb * sCh + (size_t)row * ldc + col);
                    *dst = make_float2(vx, vy);
                }
            }
        }
    }
}

// ---------------------------------------------------------------------------
// PV GEMM, NN mode: atth[m, h*96+d] = sum_tok P[m,tok] * V[tok,d].
// V read DIRECTLY from qkvh (row tok, cols 1536+h*96..+96) -- no transpose
// kernel. A (P) row-major with normal ldmatrix; B (V) staged [32 tok][96 d]
// (pitch 104 halves = 208 B; row bank stride 20 -> conflict-free) and loaded
// with ldmatrix.x4.trans, which yields exactly the col-major b-fragment.
// 256 threads, 8 warps (4m x 2n), warp tile 32x48 (6 n-groups of 8).
// K = 236 tok in 8 k-tiles of 32; A predicated at P pitch 240; B zero-filled
// for tok >= 236. 4-stage cp.async, occ 2 (stage 16896 B).
// ---------------------------------------------------------------------------
__global__ void __launch_bounds__(256, 2)
pv_gemm(const __half* __restrict__ P, const __half* __restrict__ qkvh,
        __half* __restrict__ atth)
{
    extern __shared__ __half smem[];

    const int bh = blockIdx.z;               // 0..511
    const int b = bh >> 3, h = bh & 7;
    const __half* A  = P + (size_t)bh * 236 * 240;
    const __half* Vg = qkvh + (size_t)b * 236 * 2304 + 1536 + h * 96;
    __half* C = atth + (size_t)b * 236 * 768 + h * 96;

    const int bm = blockIdx.x * 128;
    const int tid = threadIdx.x, lane = tid & 31, wid = tid >> 5;
    const int wm = wid & 3, wn = wid >> 2;   // 4 m-warps x32, 2 n-warps x48
    const int q = lane >> 2, r = lane & 3;
    const uint32_t sbase = smem_u32(smem);

    const int lt = lane >> 3, li = lane & 7;
    const int aRow = wm * 32 + (lt & 1) * 8 + li;
    const int aCol = (lt >> 1) * 16;
    // B trans addressing: row = ks + (lt&1)*8 + li (k), col = wn*48 + (lt>>1)*8 (+jp*16)
    const int bRowT = (lt & 1) * 8 + li;
    const int bColT = wn * 48 + (lt >> 1) * 8;

    float acc[2][6][4];
#pragma unroll
    for (int mt = 0; mt < 2; mt++)
#pragma unroll
        for (int j = 0; j < 6; j++)
#pragma unroll
            for (int u = 0; u < 4; u++) acc[mt][j][u] = 0.0f;

    constexpr int STAGE = 16896;             // bytes: A 10240 + B 6656

    auto issue = [&](int stage, int t) {
        const int k0 = t * 32;
#pragma unroll
        for (int i = 0; i < 2; i++) {   // A: 128 rows x 4 chunks = 512
            int cid = tid + i * 256;
            int m = cid >> 2, c8 = cid & 3;
            int gc = k0 + c8 * 8;
            int gr = bm + m;
            bool p = (gr < 236) && (gc + 8 <= 240);
            const __half* src = p ? (A + (size_t)gr * 240 + gc) : A;
            cpa16(sbase + (uint32_t)(stage * STAGE + m * 80 + c8 * 16), src, p);
        }
#pragma unroll
        for (int i = 0; i < 2; i++) {   // B: 32 tok-rows x 12 chunks = 384
            int cid = tid + i * 256;
            if (cid < 384) {
                int row = cid / 12, c = cid % 12;
                int tok = k0 + row;
                bool p = (tok < 236);
                const __half* src = p ? (Vg + (size_t)tok * 2304 + c * 8) : Vg;
                cpa16(sbase + (uint32_t)(stage * STAGE + 10240 + row * 208 + c * 16), src, p);
            }
        }
    };

    auto compute = [&](int stage) {
        const uint32_t baseA = sbase + stage * STAGE;
        const uint32_t baseB = baseA + 10240;
#pragma unroll
        for (int ks = 0; ks < 32; ks += 16) {
            uint32_t a[2][4], b[3][4];
#pragma unroll
            for (int mt = 0; mt < 2; mt++)
                LDMX4(a[mt], baseA + (uint32_t)((aRow + mt * 16) * 80 + aCol + ks * 2));
#pragma unroll
            for (int jp = 0; jp < 3; jp++)
                LDMX4T(b[jp], baseB + (uint32_t)((ks + bRowT) * 208 + (bColT + jp * 16) * 2));
#pragma unroll
            for (int mt = 0; mt < 2; mt++)
#pragma unroll
                for (int j = 0; j < 6; j++) {
                    uint32_t bb2[2] = { b[j >> 1][(j & 1) * 2], b[j >> 1][(j & 1) * 2 + 1] };
                    mma_f16(acc[mt][j], a[mt], bb2);
                }
        }
    };

    const int ntiles = 8;                    // ceil(236/32)

#pragma unroll
    for (int p = 0; p < 3; p++) {
        issue(p, p);
        asm volatile("cp.async.commit_group;" ::: "memory");
    }
    for (int t = 0; t < ntiles; t++) {
        asm volatile("cp.async.wait_group 2;" ::: "memory");
        __syncthreads();
        if (t + 3 < ntiles) issue((t + 3) & 3, t + 3);
        asm volatile("cp.async.commit_group;" ::: "memory");
        compute(t & 3);
    }

    // epilogue: cols d = wn*48 + j*8 + r*2 (< 96), rows bm + wm*32 + mt*16 + q (+8)
#pragma unroll
    for (int mt = 0; mt < 2; mt++) {
#pragma unroll
        for (int j = 0; j < 6; j++) {
            int col = wn * 48 + j * 8 + r * 2;
            int row0 = bm + wm * 32 + mt * 16 + q;
#pragma unroll
            for (int hf = 0; hf < 2; hf++) {
                int row = row0 + hf * 8;
                if (row < 236) {
                    __half2* dst = reinterpret_cast<__half2*>(C + (size_t)row * 768 + col);
                    *dst = __floats2half2_rn(acc[mt][j][hf * 2 + 0], acc[mt][j][hf * 2 + 1]);
                }
            }
        }
    }
}

// ---------------------------------------------------------------------------
// Fused QK^T*scale + block edits + softmax -> P fp16 (register-resident, R15).
// 512 threads (16 warps: 4m x 4n), CTA tile 128x256x32, warp tile 32x64.
// ---------------------------------------------------------------------------
__global__ void __launch_bounds__(512, 1)
qk_softmax(const __half* __restrict__ qkvh, __half* __restrict__ P, float scale)
{
    extern __shared__ __half smem[];
    __shared__ float red[128][4];

    const int bh = blockIdx.y;
    const int b = bh >> 3, h = bh & 7;
    const __half* A  = qkvh + (size_t)b * 236 * 2304 + h * 96;
    const __half* Bk = A + 768;
    const int bm = blockIdx.x * 128;

    const int tid = threadIdx.x, lane = tid & 31, wid = tid >> 5;
    const int wm = wid & 3, wn = wid >> 2;
    const int q = lane >> 2, r = lane & 3;
    const uint32_t sbase = smem_u32(smem);

    const int lt = lane >> 3, li = lane & 7;
    const int aRow = wm * 32 + (lt & 1) * 8 + li;
    const int aCol = (lt >> 1) * 16;
    const int bRow = wn * 64 + (lt >> 1) * 8 + li;
    const int bCol = (lt & 1) * 16;

    float acc[2][8][4];
#pragma unroll
    for (int mt = 0; mt < 2; mt++)
#pragma unroll
        for (int j = 0; j < 8; j++)
#pragma unroll
            for (int u = 0; u < 4; u++) acc[mt][j][u] = 0.0f;

    auto issue = [&](int stage, int t) {
        const int k0 = t * 32;
        {
            int m = tid >> 2, c8 = tid & 3;
            int gr = bm + m;
            bool p = (gr < 236);
            const __half* src = p ? (A + (size_t)gr * 2304 + k0 + c8 * 8) : A;
            cpa16(sbase + (uint32_t)(stage * 30720 + m * 80 + c8 * 16), src, p);
        }
#pragma unroll
        for (int i = 0; i < 2; i++) {
            int cid = tid + i * 512;
            int m = cid >> 2, c8 = cid & 3;
            bool p = (m < 236);
            const __half* src = p ? (Bk + (size_t)m * 2304 + k0 + c8 * 8) : Bk;
            cpa16(sbase + (uint32_t)(stage * 30720 + 10240 + m * 80 + c8 * 16), src, p);
        }
    };

    auto compute = [&](int stage) {
        const uint32_t baseA = sbase + stage * 30720;
        const uint32_t baseB = baseA + 10240;
#pragma unroll
        for (int ks = 0; ks < 32; ks += 16) {
            uint32_t a[2][4], b[4][4];
#pragma unroll
            for (int mt = 0; mt < 2; mt++)
                LDMX4(a[mt], baseA + (uint32_t)((aRow + mt * 16) * 80 + aCol + ks * 2));
#pragma unroll
            for (int jp = 0; jp < 4; jp++)
                LDMX4(b[jp], baseB + (uint32_t)((bRow + jp * 16) * 80 + bCol + ks * 2));
#pragma unroll
            for (int mt = 0; mt < 2; mt++)
#pragma unroll
                for (int j = 0; j < 8; j++) {
                    uint32_t bb2[2] = { b[j >> 1][(j & 1) * 2], b[j >> 1][(j & 1) * 2 + 1] };
                    mma_f16(acc[mt][j], a[mt], bb2);
                }
        }
    };

#pragma unroll
    for (int p = 0; p < 3; p++) {
        issue(p, p);
        asm volatile("cp.async.commit_group;" ::: "memory");
    }
    asm volatile("cp.async.wait_group 2;" ::: "memory"); __syncthreads(); compute(0);
    asm volatile("cp.async.wait_group 1;" ::: "memory"); __syncthreads(); compute(1);
    asm volatile("cp.async.wait_group 0;" ::: "memory"); __syncthreads(); compute(2);

#pragma unroll
    for (int mt = 0; mt < 2; mt++)
#pragma unroll
        for (int j = 0; j < 8; j++)
#pragma unroll
            for (int u = 0; u < 4; u++) acc[mt][j][u] *= scale;

    // block edits (cols 192..255 live in wn==3)
    if (wn == 3) {
#pragma unroll
        for (int mt = 0; mt < 2; mt++) {
#pragma unroll
            for (int j = 3; j <= 5; j++) {
                float tmp[4];
#pragma unroll
                for (int u = 0; u < 4; u++) {
                    float x = (r < 2) ? acc[mt][j - 2][u] : acc[mt][j - 3][u];
                    tmp[u] = __shfl_xor_sync(0xffffffffu, x, 2);
                }
                int o = j * 8 + r * 2;
#pragma unroll
                for (int u = 0; u < 4; u++) {
                    int gr = bm + wm * 32 + mt * 16 + q + (u >= 2 ? 8 : 0);
                    if (gr < 196 && o >= 24 && o < 44)
                        acc[mt][j][u] = tmp[u];
                }
            }
#pragma unroll
            for (int j = 0; j < 8; j++) {
                int col = 192 + j * 8 + r * 2;
#pragma unroll
                for (int u = 0; u < 4; u++) {
                    int gr = bm + wm * 32 + mt * 16 + q + (u >= 2 ? 8 : 0);
                    bool sub;
                    if (gr < 196)       sub = (col >= 196 && col < 216);
                    else if (gr < 216)  sub = (col >= 216 && col < 236);
                    else                sub = (col >= 196 && col < 216);
                    if (sub) acc[mt][j][u] -= 100.0f;
                }
            }
        }
    }

    // row softmax
    float mx[2][2], sm[2][2];
#pragma unroll
    for (int mt = 0; mt < 2; mt++)
#pragma unroll
        for (int hf = 0; hf < 2; hf++) {
            float m = -1e30f;
#pragma unroll
            for (int j = 0; j < 8; j++) {
                int o = j * 8 + r * 2;
                bool valid = (wn < 3) || (o < 44);
                if (valid) {
                    m = fmaxf(m, acc[mt][j][hf * 2 + 0]);
                    m = fmaxf(m, acc[mt][j][hf * 2 + 1]);
                }
            }
            m = fmaxf(m, __shfl_xor_sync(0xffffffffu, m, 1));
            m = fmaxf(m, __shfl_xor_sync(0xffffffffu, m, 2));
            mx[mt][hf] = m;
        }
    if (r == 0) {
#pragma unroll
        for (int mt = 0; mt < 2; mt++)
#pragma unroll
            for (int hf = 0; hf < 2; hf++)
                red[wm * 32 + mt * 16 + hf * 8 + q][wn] = mx[mt][hf];
    }
    __syncthreads();
#pragma unroll
    for (int mt = 0; mt < 2; mt++)
#pragma unroll
        for (int hf = 0; hf < 2; hf++) {
            int sr = wm * 32 + mt * 16 + hf * 8 + q;
            mx[mt][hf] = fmaxf(fmaxf(red[sr][0], red[sr][1]),
                               fmaxf(red[sr][2], red[sr][3]));
        }
    __syncthreads();

#pragma unroll
    for (int mt = 0; mt < 2; mt++)
#pragma unroll
        for (int hf = 0; hf < 2; hf++) {
            float s = 0.f;
#pragma unroll
            for (int j = 0; j < 8; j++) {
                int o = j * 8 + r * 2;
                bool valid = (wn < 3) || (o < 44);
                float e0 = 0.f, e1 = 0.f;
                if (valid) {
                    e0 = expf(acc[mt][j][hf * 2 + 0] - mx[mt][hf]);
                    e1 = expf(acc[mt][j][hf * 2 + 1] - mx[mt][hf]);
                }
                acc[mt][j][hf * 2 + 0] = e0;
                acc[mt][j][hf * 2 + 1] = e1;
                s += e0 + e1;
            }
            s += __shfl_xor_sync(0xffffffffu, s, 1);
            s += __shfl_xor_sync(0xffffffffu, s, 2);
            sm[mt][hf] = s;
        }
    if (r == 0) {
#pragma unroll
        for (int mt = 0; mt < 2; mt++)
#pragma unroll
            for (int hf = 0; hf < 2; hf++)
                red[wm * 32 + mt * 16 + hf * 8 + q][wn] = sm[mt][hf];
    }
    __syncthreads();
#pragma unroll
    for (int mt = 0; mt < 2; mt++)
#pragma unroll
        for (int hf = 0; hf < 2; hf++) {
            int sr = wm * 32 + mt * 16 + hf * 8 + q;
            sm[mt][hf] = red[sr][0] + red[sr][1] + red[sr][2] + red[sr][3];
        }

#pragma unroll
    for (int mt = 0; mt < 2; mt++)
#pragma unroll
        for (int hf = 0; hf < 2; hf++) {
            int gr = bm + wm * 32 + mt * 16 + hf * 8 + q;
            if (gr >= 236) continue;
            __half* prow = P + ((size_t)bh * 236 + gr) * 240;
            float inv = 1.0f / sm[mt][hf];
#pragma unroll
            for (int j = 0; j < 8; j++) {
                int col = wn * 64 + j * 8 + r * 2;
                if (col >= 240) continue;
                float v0 = 0.f, v1 = 0.f;
                if (col < 236) {
                    v0 = acc[mt][j][hf * 2 + 0] * inv;
                    v1 = acc[mt][j][hf * 2 + 1] * inv;
                }
                *reinterpret_cast<__half2*>(prow + col) = __floats2half2_rn(v0, v1);
            }
        }
}

// ---------------------------------------------------------------------------
// fp32 -> fp16 conversion (4 floats / thread)
// ---------------------------------------------------------------------------
__global__ void cvt_h(const float* __restrict__ in, __half* __restrict__ out, int n4)
{
    int i = blockIdx.x * blockDim.x + threadIdx.x;
    if (i < n4) {
        float4 v = reinterpret_cast<const float4*>(in)[i];
        uint2 u;
        __half2 h0 = __floats2half2_rn(v.x, v.y);
        __half2 h1 = __floats2half2_rn(v.z, v.w);
        u.x = *reinterpret_cast<uint32_t*>(&h0);
        u.y = *reinterpret_cast<uint32_t*>(&h1);
        reinterpret_cast<uint2*>(out)[i] = u;
    }
}

// ---------------------------------------------------------------------------
extern "C" void kernel_launch(void* const* d_in, const int* in_sizes, int n_in,
                              void* d_out, int out_size)
{
    const float* x      = (const float*)d_in[0];   // [64,236,768]
    const float* qkv_w  = (const float*)d_in[1];   // [2304,768]
    const float* proj_w = (const float*)d_in[2];   // [768,768]
    const float* proj_b = (const float*)d_in[3];   // [768]
    float* out = (float*)d_out;                    // [64,236,768]

    __half *qkvh, *P, *atth, *xh, *wh, *pwh;
    cudaGetSymbolAddress((void**)&qkvh, g_qkvh);
    cudaGetSymbolAddress((void**)&P,    g_P);
    cudaGetSymbolAddress((void**)&atth, g_atth);
    cudaGetSymbolAddress((void**)&xh,   g_xh);
    cudaGetSymbolAddress((void**)&wh,   g_wh);
    cudaGetSymbolAddress((void**)&pwh,  g_pwh);

    const int SMEM    = 81920;     // hgemm: 4 x 20480
    const int SMEM_QK = 92160;     // qk_softmax: 3 x 30720
    const int SMEM_PV = 67584;     // pv_gemm: 4 x 16896
    cudaFuncSetAttribute(hgemm<true,  false>, cudaFuncAttributeMaxDynamicSharedMemorySize, SMEM);
    cudaFuncSetAttribute(hgemm<false, true>,  cudaFuncAttributeMaxDynamicSharedMemorySize, SMEM);
    cudaFuncSetAttribute(qk_softmax, cudaFuncAttributeMaxDynamicSharedMemorySize, SMEM_QK);
    cudaFuncSetAttribute(pv_gemm,    cudaFuncAttributeMaxDynamicSharedMemorySize, SMEM_PV);

    const float scale = 0.10206207261596575f;      // 1/sqrt(96)

    // 0) convert inputs to fp16
    cvt_h<<<(15104 * 768 / 4 + 255) / 256, 256>>>(x, xh, 15104 * 768 / 4);
    cvt_h<<<(2304 * 768 / 4 + 255) / 256, 256>>>(qkv_w, wh, 2304 * 768 / 4);
    cvt_h<<<(768 * 768 / 4 + 255) / 256, 256>>>(proj_w, pwh, 768 * 768 / 4);

    // 1) qkvh = x @ qkv_w^T            [15104 x 2304], K=768, fp16 out
    hgemm<true, false><<<dim3(118, 18, 1), 256, SMEM>>>(
        xh, wh, nullptr, qkvh,
        15104, 2304, 768, 768, 768, 2304,
        1, 0, 0, 0, 0, 0, 0, 1.0f);

    // 2) fused QK^T*scale + edits + softmax -> P fp16 (padded 240)
    qk_softmax<<<dim3(2, 512), 512, SMEM_QK>>>(qkvh, P, scale);

    // 3) atth = P @ V (NN, V direct from qkvh -- no transpose kernel)
    pv_gemm<<<dim3(2, 1, 512), 256, SMEM_PV>>>(P, qkvh, atth);

    // 4) out = atth @ proj_w^T + proj_b  [15104 x 768], K=768, fp32 out + bias
    hgemm<false, true><<<dim3(118, 6, 1), 256, SMEM>>>(
        atth, pwh, proj_b, out,
        15104, 768, 768, 768, 768, 768,
        1, 0, 0, 0, 0, 0, 0, 1.0f);
}